// round 13
// baseline (speedup 1.0000x reference)
#include <cuda_runtime.h>
#include <cuda_bf16.h>
#include <cuda_fp16.h>
#include <math.h>
#include <stdint.h>

// ---------------------------------------------------------------------------
// DecoderLayerWithContext — Round 13
// vs R9 (971us, hgemm 64x32-warp 2CTA) and R12 (1117us, ILP@64x32 1CTA FAIL):
// hgemm now 128x256 CTA tile, 64x64 warp tile => MMA:LDSM doubled
// (8 LDSM / 32 MMA vs 6/16), cp.async 48B/MMA. smem/MMA 256->176B.
// 3-stage ring + R9 sync scheme. flash/prep/ln verbatim from R9.
// ---------------------------------------------------------------------------

namespace cfg {
constexpr int E  = 1024;
constexpr int NH = 16;
constexpr int HD = 64;
constexpr int B  = 2;
constexpr int T  = 2048;
constexpr int S  = 2048;
constexpr int BH = B * NH;
constexpr float SC2 = 0.03125f * 1.44269504f;   // (1/sqrt(E)) * log2(e)
}

// -------------------------- device scratch ---------------------------------
__device__ float    g_x1[cfg::B * cfg::T * cfg::E];
__device__ float    g_x2[cfg::B * cfg::T * cfg::E];
__device__ uint16_t g_a [(size_t)4  * 1024 * 1024];
__device__ uint16_t g_c [(size_t)4  * 1024 * 1024];
__device__ uint16_t g_q [(size_t)4  * 1024 * 1024];
__device__ uint16_t g_f [(size_t)16 * 1024 * 1024];
__device__ uint16_t g_w [(size_t)16 * 1024 * 1024];

// g_w layout (units of 1M = E*E halves):
// 0:Wq_s 1:Wk_s 2:Wv_s 3:proj_s 4:Wq_c 5:Wk_c 6:Wv_c 7:proj_c 8..11:w1 12..15:w2
constexpr size_t WU = (size_t)1024 * 1024;

// -------------------------- asm helpers ------------------------------------
__device__ __forceinline__ uint32_t smem_u32(const void* p) {
    uint32_t a;
    asm("{ .reg .u64 t; cvta.to.shared.u64 t, %1; cvt.u32.u64 %0, t; }" : "=r"(a) : "l"(p));
    return a;
}
#define CP16(s, g) \
    asm volatile("cp.async.cg.shared.global [%0], [%1], 16;" :: "r"(s), "l"(g))
#define CP_COMMIT()  asm volatile("cp.async.commit_group;" ::: "memory")
#define CP_WAIT0()   asm volatile("cp.async.wait_group 0;" ::: "memory")
#define CP_WAIT1()   asm volatile("cp.async.wait_group 1;" ::: "memory")

#define LDSM4(r, addr)                                                        \
    asm volatile("ldmatrix.sync.aligned.m8n8.x4.shared.b16 {%0,%1,%2,%3}, [%4];" \
        : "=r"((r)[0]), "=r"((r)[1]), "=r"((r)[2]), "=r"((r)[3]) : "r"(addr))
#define LDSM4T(r, addr)                                                       \
    asm volatile("ldmatrix.sync.aligned.m8n8.x4.trans.shared.b16 {%0,%1,%2,%3}, [%4];" \
        : "=r"((r)[0]), "=r"((r)[1]), "=r"((r)[2]), "=r"((r)[3]) : "r"(addr))

#define MMAH(d, a, b0, b1)                                                    \
    asm("mma.sync.aligned.m16n8k16.row.col.f32.f16.f16.f32 "                  \
        "{%0,%1,%2,%3},{%4,%5,%6,%7},{%8,%9},{%0,%1,%2,%3};"                  \
        : "+f"((d)[0]), "+f"((d)[1]), "+f"((d)[2]), "+f"((d)[3])              \
        : "r"((a)[0]), "r"((a)[1]), "r"((a)[2]), "r"((a)[3]), "r"(b0), "r"(b1))

__device__ __forceinline__ uint32_t packh2(float lo, float hi) {
    __half2 h = __floats2half2_rn(lo, hi);
    return *reinterpret_cast<uint32_t*>(&h);
}
__device__ __forceinline__ unsigned short h16(float x) {
    __half h = __float2half_rn(x);
    return *reinterpret_cast<unsigned short*>(&h);
}
__device__ __forceinline__ float gelu_f(float x) {
    return 0.5f * x * (1.0f + erff(x * 0.7071067811865475f));
}

// ---------------------------------------------------------------------------
// fp16 HMMA GEMM: C[M,N] = epi(A[M,K] * B[N,K]^T)
// CTA tile 128(M) x 256(N), warp tile 64x64 (8 warps, 2x4 grid).
// K chunks of 64; stage = A 16KB + B 32KB = 48KB; 3-stage cp.async ring,
// one syncthreads per chunk (R9-proven scheme). 1 CTA/SM (acc=128 regs).
// ---------------------------------------------------------------------------
constexpr int H_OFF_B = 16384;            // B tile after A (16KB)
constexpr int H_STAGE = 49152;            // 48KB per stage
constexpr int GEMM_SMEM = 3 * H_STAGE + 1024;

__global__ void __launch_bounds__(256, 1)
hgemm(const uint16_t* __restrict__ A, const uint16_t* __restrict__ Bm,
      const float* __restrict__ bias, const float* __restrict__ res,
      float* __restrict__ C, uint16_t* __restrict__ Ch,
      int N, int K, int do_gelu) {
    extern __shared__ uint8_t dsm[];
    uint8_t* tiles = (uint8_t*)(((uintptr_t)dsm + 1023) & ~(uintptr_t)1023);
    const uint32_t tb = smem_u32(tiles);

    const int tid  = threadIdx.x;
    const int lane = tid & 31;
    const int wid  = tid >> 5;
    const int wr   = wid >> 2;    // 0..1  (M)
    const int wc   = wid & 3;     // 0..3  (N)
    const int row0 = blockIdx.y * 128;
    const int col0 = blockIdx.x * 256;

    // ---- cp.async geometry ----
    // A: 2 threads per row (128 rows), 64B each
    const int lrow = tid >> 1, lhalf = tid & 1;
    uint32_t soA[4];
#pragma unroll
    for (int i = 0; i < 4; i++) {
        uint32_t o = (uint32_t)lrow * 128 + (uint32_t)lhalf * 64 + i * 16;
        soA[i] = o ^ ((o >> 3) & 0x70);
    }
    const size_t a_base = (size_t)(row0 + lrow) * K + lhalf * 32;
    // B: 1 thread per row (256 rows), full 128B row
    const uint32_t xrB = (uint32_t)(tid & 7) * 16;
    const uint32_t rowB = (uint32_t)tid * 128;
    const size_t b_base = (size_t)(col0 + tid) * K;

    // ---- fragment geometry ----
    const int ka = (lane >> 4) * 16;
    const int kb = ((lane >> 3) & 1) * 16;
    uint32_t aoff[4], xA[4];
#pragma unroll
    for (int mt = 0; mt < 4; mt++) {
        int r = wr * 64 + mt * 16 + (lane & 15);
        aoff[mt] = (uint32_t)r * 128;
        xA[mt] = (uint32_t)(r & 7) * 16;
    }
    uint32_t boff[4], xB[4];
#pragma unroll
    for (int pb = 0; pb < 4; pb++) {
        int r = wc * 64 + pb * 16 + ((lane >> 4) & 1) * 8 + (lane & 7);
        boff[pb] = (uint32_t)r * 128;
        xB[pb] = (uint32_t)(r & 7) * 16;
    }

    float acc[4][8][4];
#pragma unroll
    for (int mt = 0; mt < 4; mt++)
#pragma unroll
        for (int nt = 0; nt < 8; nt++)
#pragma unroll
            for (int e = 0; e < 4; e++) acc[mt][nt][e] = 0.0f;

    const int NC = K >> 6;
    // prologue: chunks 0,1 into stages 0,1
#pragma unroll
    for (int pc = 0; pc < 2; pc++) {
        if (pc < NC) {
            const uint32_t st = tb + pc * H_STAGE;
            const int kc = pc << 6;
#pragma unroll
            for (int i = 0; i < 4; i++)
                CP16(st + soA[i], A + a_base + kc + i * 8);
#pragma unroll
            for (int i = 0; i < 8; i++) {
                uint32_t o = rowB + i * 16;
                CP16(st + H_OFF_B + (o ^ xrB), Bm + b_base + kc + i * 8);
            }
            CP_COMMIT();
        }
    }

    int stage = 0;
    for (int c = 0; c < NC; c++) {
        if (c + 1 < NC) CP_WAIT1(); else CP_WAIT0();
        __syncthreads();   // chunk c ready; stage (c+2)%3 free

        if (c + 2 < NC) {
            int pst = stage + 2; if (pst >= 3) pst -= 3;
            const uint32_t st = tb + pst * H_STAGE;
            const int kc = (c + 2) << 6;
#pragma unroll
            for (int i = 0; i < 4; i++)
                CP16(st + soA[i], A + a_base + kc + i * 8);
#pragma unroll
            for (int i = 0; i < 8; i++) {
                uint32_t o = rowB + i * 16;
                CP16(st + H_OFF_B + (o ^ xrB), Bm + b_base + kc + i * 8);
            }
            CP_COMMIT();
        }

        const uint32_t sb = tb + stage * H_STAGE;
#pragma unroll
        for (int ks = 0; ks < 4; ks++) {
            uint32_t af[4][4], bf[4][4];
            const uint32_t cba = (uint32_t)(ks * 32 + ka);
#pragma unroll
            for (int mt = 0; mt < 4; mt++)
                LDSM4(af[mt], sb + aoff[mt] + (cba ^ xA[mt]));
            const uint32_t cbb = (uint32_t)(ks * 32 + kb);
#pragma unroll
            for (int pb = 0; pb < 4; pb++)
                LDSM4(bf[pb], sb + H_OFF_B + boff[pb] + (cbb ^ xB[pb]));
            // 32 independent MMAs (each acc tile touched once per ks)
#pragma unroll
            for (int pb = 0; pb < 4; pb++)
#pragma unroll
                for (int mt = 0; mt < 4; mt++) {
                    MMAH(acc[mt][2 * pb],     af[mt], bf[pb][0], bf[pb][1]);
                    MMAH(acc[mt][2 * pb + 1], af[mt], bf[pb][2], bf[pb][3]);
                }
        }
        if (++stage == 3) stage = 0;
    }

    const int mrow = lane >> 2;
    const int ncol = (lane & 3) * 2;
#pragma unroll
    for (int mt = 0; mt < 4; mt++) {
#pragma unroll
        for (int half = 0; half < 2; half++) {
            const int r = row0 + wr * 64 + mt * 16 + mrow + half * 8;
#pragma unroll
            for (int nt = 0; nt < 8; nt++) {
                float v0 = acc[mt][nt][half * 2 + 0];
                float v1 = acc[mt][nt][half * 2 + 1];
                const int cc = col0 + wc * 64 + nt * 8 + ncol;
                if (bias) { v0 += bias[cc]; v1 += bias[cc + 1]; }
                if (do_gelu) { v0 = gelu_f(v0); v1 = gelu_f(v1); }
                if (res) {
                    v0 += res[(size_t)r * N + cc];
                    v1 += res[(size_t)r * N + cc + 1];
                }
                if (C) *(float2*)(C + (size_t)r * N + cc) = make_float2(v0, v1);
                if (Ch) *(uint32_t*)(Ch + (size_t)r * N + cc) = packh2(v0, v1);
            }
        }
    }
}

// ---------------------------------------------------------------------------
// Fused flash attention, fp16, 3-stage KV ring (verbatim from R9, validated).
// ---------------------------------------------------------------------------
constexpr int F_KV0 = 16384;
constexpr int F_V   = 16384;
constexpr int F_STG = 32768;
constexpr int FLASH_SMEM = 16384 + 3 * F_STG + 1024;

__global__ void __launch_bounds__(256, 1)
flash_h(const uint16_t* __restrict__ Q, const uint16_t* __restrict__ Kp,
        const uint16_t* __restrict__ Vp, uint16_t* __restrict__ Oh,
        int Tq, int Tk, int strQ, int strKV, int causal) {
    extern __shared__ uint8_t dsm[];
    uint8_t* basep = (uint8_t*)(((uintptr_t)dsm + 1023) & ~(uintptr_t)1023);
    const uint32_t tb = smem_u32(basep);

    const int bh = blockIdx.y;
    const int b = bh >> 4, h = bh & 15;
    int it = blockIdx.x;
    if (causal) it = (int)gridDim.x - 1 - it;
    const int i0 = it * 128;
    const int NJ = causal ? (it + 1) : (Tk >> 7);

    const int tid = threadIdx.x;
    const int lane = tid & 31;
    const int wid = tid >> 5;

    const int lrow = tid >> 1, lhalf = tid & 1;
    uint32_t so[4];
#pragma unroll
    for (int i = 0; i < 4; i++) {
        uint32_t o = (uint32_t)lrow * 128 + (uint32_t)lhalf * 64 + i * 16;
        so[i] = o ^ ((o >> 3) & 0x70);
    }
    const size_t qg = (size_t)(b * Tq + i0 + lrow) * strQ + h * cfg::HD + lhalf * 32;
    const size_t kg = (size_t)(b * Tk + lrow) * strKV + h * cfg::HD + lhalf * 32;

#pragma unroll
    for (int i = 0; i < 4; i++) CP16(tb + so[i], Q + qg + i * 8);
    {
        const uint32_t st = tb + F_KV0;
#pragma unroll
        for (int i = 0; i < 4; i++) {
            CP16(st + so[i],       Kp + kg + i * 8);
            CP16(st + F_V + so[i], Vp + kg + i * 8);
        }
        CP_COMMIT();
    }
    if (1 < NJ) {
        const uint32_t st = tb + F_KV0 + F_STG;
        const size_t kg1 = kg + (size_t)128 * strKV;
#pragma unroll
        for (int i = 0; i < 4; i++) {
            CP16(st + so[i],       Kp + kg1 + i * 8);
            CP16(st + F_V + so[i], Vp + kg1 + i * 8);
        }
        CP_COMMIT();
    }

    const int arow = wid * 16 + (lane & 15);
    const uint32_t aoff = (uint32_t)arow * 128;
    const uint32_t axr  = (uint32_t)(arow & 7) * 16;
    const int ka = (lane >> 4) * 16;
    const int nrow_b = ((lane >> 4) & 1) * 8 + (lane & 7);
    const int kb = ((lane >> 3) & 1) * 16;
    const int vm = lane >> 3;
    const int vrow_b = (vm & 1) * 8 + (lane & 7);
    const int vcol_b = (vm >> 1) * 16;

    uint32_t qf[4][4];
    float accO[8][4];
#pragma unroll
    for (int nt = 0; nt < 8; nt++)
#pragma unroll
        for (int e = 0; e < 4; e++) accO[nt][e] = 0.0f;
    float m2[2] = {-3.0e38f, -3.0e38f};
    float lsum[2] = {0.0f, 0.0f};

    const int mrow = lane >> 2;
    const int cb = (lane & 3) * 2;
    const int irow0 = i0 + wid * 16 + mrow;
    const int irow1 = irow0 + 8;

    int stage = 0;
    for (int jt = 0; jt < NJ; jt++) {
        if (jt + 1 < NJ) CP_WAIT1(); else CP_WAIT0();
        __syncthreads();

        if (jt + 2 < NJ) {
            int pst = stage + 2; if (pst >= 3) pst -= 3;
            const uint32_t st = tb + F_KV0 + pst * F_STG;
            const size_t kgj = kg + (size_t)(jt + 2) * 128 * strKV;
#pragma unroll
            for (int i = 0; i < 4; i++) {
                CP16(st + so[i],       Kp + kgj + i * 8);
                CP16(st + F_V + so[i], Vp + kgj + i * 8);
            }
            CP_COMMIT();
        }

        if (jt == 0) {
#pragma unroll
            for (int ks = 0; ks < 4; ks++)
                LDSM4(qf[ks], tb + aoff + (((uint32_t)(ks * 32 + ka)) ^ axr));
        }
        const uint32_t sb = tb + F_KV0 + stage * F_STG;

        float accS[16][4];
#pragma unroll
        for (int nt = 0; nt < 16; nt++)
#pragma unroll
            for (int e = 0; e < 4; e++) accS[nt][e] = 0.0f;

#pragma unroll
        for (int ks = 0; ks < 4; ks++) {
            const uint32_t cbb = (uint32_t)(ks * 32 + kb);
#pragma unroll
            for (int ntp = 0; ntp < 8; ntp++) {
                const int r = ntp * 16 + nrow_b;
                uint32_t bf4[4];
                LDSM4(bf4, sb + (uint32_t)r * 128 + (cbb ^ ((uint32_t)(r & 7) * 16)));
                MMAH(accS[2 * ntp],     qf[ks], bf4[0], bf4[1]);
                MMAH(accS[2 * ntp + 1], qf[ks], bf4[2], bf4[3]);
            }
        }

        const int j0 = jt * 128;
        const bool maskTile = causal && (jt == NJ - 1);
#pragma unroll
        for (int nt = 0; nt < 16; nt++)
#pragma unroll
            for (int e = 0; e < 4; e++) accS[nt][e] *= cfg::SC2;
        if (maskTile) {
#pragma unroll
            for (int nt = 0; nt < 16; nt++) {
                const int jc = j0 + nt * 8 + cb;
                if (jc     > irow0) accS[nt][0] = -3.0e38f;
                if (jc + 1 > irow0) accS[nt][1] = -3.0e38f;
                if (jc     > irow1) accS[nt][2] = -3.0e38f;
                if (jc + 1 > irow1) accS[nt][3] = -3.0e38f;
            }
        }

        float mx0 = -3.0e38f, mx1 = -3.0e38f;
#pragma unroll
        for (int nt = 0; nt < 16; nt++) {
            mx0 = fmaxf(mx0, fmaxf(accS[nt][0], accS[nt][1]));
            mx1 = fmaxf(mx1, fmaxf(accS[nt][2], accS[nt][3]));
        }
        mx0 = fmaxf(mx0, __shfl_xor_sync(0xffffffffu, mx0, 1));
        mx0 = fmaxf(mx0, __shfl_xor_sync(0xffffffffu, mx0, 2));
        mx1 = fmaxf(mx1, __shfl_xor_sync(0xffffffffu, mx1, 1));
        mx1 = fmaxf(mx1, __shfl_xor_sync(0xffffffffu, mx1, 2));
        const float mn0 = fmaxf(m2[0], mx0);
        const float mn1 = fmaxf(m2[1], mx1);
        const float al0 = exp2f(m2[0] - mn0);
        const float al1 = exp2f(m2[1] - mn1);
        m2[0] = mn0; m2[1] = mn1;

        float s0 = 0.0f, s1 = 0.0f;
#pragma unroll
        for (int nt = 0; nt < 16; nt++) {
            float p0 = exp2f(accS[nt][0] - mn0);
            float p1 = exp2f(accS[nt][1] - mn0);
            float p2 = exp2f(accS[nt][2] - mn1);
            float p3 = exp2f(accS[nt][3] - mn1);
            accS[nt][0] = p0; accS[nt][1] = p1;
            accS[nt][2] = p2; accS[nt][3] = p3;
            s0 += p0 + p1;
            s1 += p2 + p3;
        }
        s0 += __shfl_xor_sync(0xffffffffu, s0, 1);
        s0 += __shfl_xor_sync(0xffffffffu, s0, 2);
        s1 += __shfl_xor_sync(0xffffffffu, s1, 1);
        s1 += __shfl_xor_sync(0xffffffffu, s1, 2);
        lsum[0] = lsum[0] * al0 + s0;
        lsum[1] = lsum[1] * al1 + s1;

#pragma unroll
        for (int nt = 0; nt < 8; nt++) {
            accO[nt][0] *= al0; accO[nt][1] *= al0;
            accO[nt][2] *= al1; accO[nt][3] *= al1;
        }

#pragma unroll
        for (int ks = 0; ks < 8; ks++) {
            uint32_t ph[4];
#pragma unroll
            for (int q = 0; q < 2; q++) {
                ph[2 * q]     = packh2(accS[2 * ks + q][0], accS[2 * ks + q][1]);
                ph[2 * q + 1] = packh2(accS[2 * ks + q][2], accS[2 * ks + q][3]);
            }
            const int jr = ks * 16 + vrow_b;
            const uint32_t roff = (uint32_t)jr * 128;
            const uint32_t xr = (uint32_t)(jr & 7) * 16;
#pragma unroll
            for (int ntp = 0; ntp < 4; ntp++) {
                uint32_t vf4[4];
                LDSM4T(vf4, sb + F_V + roff + (((uint32_t)(ntp * 32 + vcol_b)) ^ xr));
                MMAH(accO[2 * ntp],     ph, vf4[0], vf4[1]);
                MMAH(accO[2 * ntp + 1], ph, vf4[2], vf4[3]);
            }
        }
        if (++stage == 3) stage = 0;
    }

    const float li0 = 1.0f / lsum[0];
    const float li1 = 1.0f / lsum[1];
#pragma unroll
    for (int nt = 0; nt < 8; nt++) {
        const int d = h * cfg::HD + nt * 8 + cb;
        const size_t o0 = (size_t)(b * Tq + irow0) * cfg::E + d;
        const size_t o1 = (size_t)(b * Tq + irow1) * cfg::E + d;
        *(uint32_t*)(Oh + o0) = packh2(accO[nt][0] * li0, accO[nt][1] * li0);
        *(uint32_t*)(Oh + o1) = packh2(accO[nt][2] * li1, accO[nt][3] * li1);
    }
}

// ---------------------------------------------------------------------------
// Weight prep: ALL transposes (fp32 [K,N] -> fp16 [N,K]) in ONE launch.
// ---------------------------------------------------------------------------
__global__ void prep_weights(
    const float* __restrict__ Wq_s, const float* __restrict__ Wk_s,
    const float* __restrict__ Wv_s, const float* __restrict__ proj_s,
    const float* __restrict__ Wq_c, const float* __restrict__ Wk_c,
    const float* __restrict__ Wv_c, const float* __restrict__ proj_c,
    const float* __restrict__ w1,   const float* __restrict__ w2,
    uint16_t* __restrict__ Wdst) {
    __shared__ float tile[32][33];
    const int id = blockIdx.x;
    const float* W;
    uint16_t* H;
    int n0, k0, Kd, Nd;
    if (id < 8192) {
        const int w = id >> 10, t = id & 1023;
        const float* srcs[8] = {Wq_s, Wk_s, Wv_s, proj_s, Wq_c, Wk_c, Wv_c, proj_c};
        W = srcs[w];
        H = Wdst + (size_t)w * WU;
        n0 = (t & 31) * 32; k0 = (t >> 5) * 32;
        Kd = cfg::E; Nd = cfg::E;
    } else if (id < 12288) {
        const int t = id - 8192;                 // w1: [E,4E] -> [4E,E]
        W = w1; H = Wdst + 8 * WU;
        n0 = (t & 127) * 32; k0 = (t >> 7) * 32;
        Kd = cfg::E; Nd = 4 * cfg::E;
    } else {
        const int t = id - 12288;                // w2: [4E,E] -> [E,4E]
        W = w2; H = Wdst + 12 * WU;
        n0 = (t & 31) * 32; k0 = (t >> 5) * 32;
        Kd = 4 * cfg::E; Nd = cfg::E;
    }
    const int tx = threadIdx.x, ty = threadIdx.y;
    for (int r = ty; r < 32; r += 8)
        tile[r][tx] = W[(size_t)(k0 + r) * Nd + n0 + tx];
    __syncthreads();
    for (int r = ty; r < 32; r += 8)
        H[(size_t)(n0 + r) * Kd + k0 + tx] = h16(tile[tx][r]);
}

// ---------------------------------------------------------------------------
// LayerNorm -> fp16 ; fp32 -> fp16 copy
// ---------------------------------------------------------------------------
__global__ void ln_h(const float* __restrict__ X, const float* __restrict__ gam,
                     const float* __restrict__ bet, uint16_t* __restrict__ H) {
    __shared__ float red[256];
    const int row = blockIdx.x;
    const int tid = threadIdx.x;
    const float4 v = ((const float4*)(X + (size_t)row * cfg::E))[tid];

    float s = v.x + v.y + v.z + v.w;
    red[tid] = s; __syncthreads();
    for (int off = 128; off; off >>= 1) {
        if (tid < off) red[tid] += red[tid + off];
        __syncthreads();
    }
    const float mu = red[0] * (1.0f / cfg::E);
    __syncthreads();

    const float dx = v.x - mu, dy = v.y - mu, dz = v.z - mu, dw = v.w - mu;
    red[tid] = dx*dx + dy*dy + dz*dz + dw*dw; __syncthreads();
    for (int off = 128; off; off >>= 1) {
        if (tid < off) red[tid] += red[tid + off];
        __syncthreads();
    }
    const float var = red[0] * (1.0f / cfg::E);
    const float r = rsqrtf(var + 1e-5f);

    const float4 g4 = ((const float4*)gam)[tid];
    const float4 b4 = ((const float4*)bet)[tid];
    ushort4 o;
    o.x = h16(dx * r * g4.x + b4.x);
    o.y = h16(dy * r * g4.y + b4.y);
    o.z = h16(dz * r * g4.z + b4.z);
    o.w = h16(dw * r * g4.w + b4.w);
    ((ushort4*)(H + (size_t)row * cfg::E))[tid] = o;
}

__global__ void split_h(const float* __restrict__ X, uint16_t* __restrict__ H, int n4) {
    const int i = blockIdx.x * 256 + threadIdx.x;
    if (i >= n4) return;
    const float4 v = ((const float4*)X)[i];
    ushort4 o;
    o.x = h16(v.x); o.y = h16(v.y); o.z = h16(v.z); o.w = h16(v.w);
    ((ushort4*)H)[i] = o;
}

// ---------------------------------------------------------------------------
// Launch sequence
// ---------------------------------------------------------------------------
extern "C" void kernel_launch(void* const* d_in, const int* in_sizes, int n_in,
                              void* d_out, int out_size) {
    using namespace cfg;
    const float* x        = (const float*)d_in[0];
    const float* context  = (const float*)d_in[1];
    const float* ln1_g    = (const float*)d_in[2];
    const float* ln1_b    = (const float*)d_in[3];
    const float* ln2_g    = (const float*)d_in[4];
    const float* ln2_b    = (const float*)d_in[5];
    const float* ln3_g    = (const float*)d_in[6];
    const float* ln3_b    = (const float*)d_in[7];
    const float* Wq_s     = (const float*)d_in[8];
    const float* Wk_s     = (const float*)d_in[9];
    const float* Wv_s     = (const float*)d_in[10];
    const float* proj_s_w = (const float*)d_in[11];
    const float* proj_s_b = (const float*)d_in[12];
    const float* Wq_c     = (const float*)d_in[13];
    const float* Wk_c     = (const float*)d_in[14];
    const float* Wv_c     = (const float*)d_in[15];
    const float* proj_c_w = (const float*)d_in[16];
    const float* proj_c_b = (const float*)d_in[17];
    const float* w1       = (const float*)d_in[18];
    const float* b1       = (const float*)d_in[19];
    const float* w2       = (const float*)d_in[20];
    const float* b2       = (const float*)d_in[21];
    float* out = (float*)d_out;

    float *px1, *px2;
    uint16_t *ah, *ch, *qh, *fh, *wh;
    cudaGetSymbolAddress((void**)&px1, g_x1);
    cudaGetSymbolAddress((void**)&px2, g_x2);
    cudaGetSymbolAddress((void**)&ah, g_a);
    cudaGetSymbolAddress((void**)&ch, g_c);
    cudaGetSymbolAddress((void**)&qh, g_q);
    cudaGetSymbolAddress((void**)&fh, g_f);
    cudaGetSymbolAddress((void**)&wh, g_w);

    cudaFuncSetAttribute(hgemm,   cudaFuncAttributeMaxDynamicSharedMemorySize, GEMM_SMEM);
    cudaFuncSetAttribute(flash_h, cudaFuncAttributeMaxDynamicSharedMemorySize, FLASH_SMEM);

    const int M = B * T;
    const dim3 gE   (E / 256,     M / 128);   // (4, 32)
    const dim3 gQKV (3 * E / 256, M / 128);   // (12, 32)
    const dim3 gKV  (2 * E / 256, M / 128);   // (8, 32)
    const dim3 g4E  (4 * E / 256, M / 128);   // (16, 32)
    const dim3 gfl  (T / 128, BH);
    const int nME4 = (M * E) / 4;
    const dim3 tbt(32, 8);

    // ---- one-shot prep: all weights + context ----
    prep_weights<<<16384, tbt>>>(Wq_s, Wk_s, Wv_s, proj_s_w,
                                 Wq_c, Wk_c, Wv_c, proj_c_w, w1, w2, wh);
    split_h<<<(nME4 + 255) / 256, 256>>>(context, ch, nME4);

    // ---- self attention (causal): merged QKV (units 0,1,2) ----
    ln_h<<<M, 256>>>(x, ln1_g, ln1_b, ah);
    hgemm<<<gQKV, 256, GEMM_SMEM>>>(ah, wh, nullptr, nullptr,
                                    nullptr, fh, 3 * E, E, 0);
    flash_h<<<gfl, 256, FLASH_SMEM>>>(fh, fh + E, fh + 2 * E, qh, T, S, 3 * E, 3 * E, 1);
    hgemm<<<gE, 256, GEMM_SMEM>>>(qh, wh + 3 * WU, proj_s_b, x, px1, nullptr, E, E, 0);

    // ---- cross attention (context NOT normalized): merged KV (units 5,6) ----
    ln_h<<<M, 256>>>(px1, ln2_g, ln2_b, ah);
    hgemm<<<gE, 256, GEMM_SMEM>>>(ah, wh + 4 * WU, nullptr, nullptr, nullptr, qh, E, E, 0);
    hgemm<<<gKV, 256, GEMM_SMEM>>>(ch, wh + 5 * WU, nullptr, nullptr, nullptr, fh, 2 * E, E, 0);
    flash_h<<<gfl, 256, FLASH_SMEM>>>(qh, fh, fh + E, ah, T, S, E, 2 * E, 0);
    hgemm<<<gE, 256, GEMM_SMEM>>>(ah, wh + 7 * WU, proj_c_b, px1, px2, nullptr, E, E, 0);

    // ---- FFN ----
    ln_h<<<M, 256>>>(px2, ln3_g, ln3_b, qh);
    hgemm<<<g4E, 256, GEMM_SMEM>>>(qh, wh + 8 * WU, b1, nullptr, nullptr, fh, 4 * E, E, 1);
    hgemm<<<gE, 256, GEMM_SMEM>>>(fh, wh + 12 * WU, b2, px2, out, nullptr, E, 4 * E, 0);
}

// round 15
// speedup vs baseline: 1.2444x; 1.2444x over previous
#include <cuda_runtime.h>
#include <cuda_bf16.h>
#include <cuda_fp16.h>
#include <math.h>
#include <stdint.h>

// ---------------------------------------------------------------------------
// DecoderLayerWithContext — Round 15
// R14 failed on a buffer-overlap: early cross-KV GEMM wrote fh[8M,16M) while
// the self-attn QKV GEMM writes fh[0,12M). Fix: dedicated g_kv buffer for
// cross-attention K/V. hgemm/flash are the R9-validated configs.
// ---------------------------------------------------------------------------

namespace cfg {
constexpr int E  = 1024;
constexpr int NH = 16;
constexpr int HD = 64;
constexpr int B  = 2;
constexpr int T  = 2048;
constexpr int S  = 2048;
constexpr int BH = B * NH;
constexpr float SC2 = 0.03125f * 1.44269504f;   // (1/sqrt(E)) * log2(e)
}

// -------------------------- device scratch ---------------------------------
__device__ float    g_x1[cfg::B * cfg::T * cfg::E];
__device__ float    g_x2[cfg::B * cfg::T * cfg::E];
__device__ uint16_t g_a [(size_t)4  * 1024 * 1024];
__device__ uint16_t g_c [(size_t)4  * 1024 * 1024];
__device__ uint16_t g_q [(size_t)4  * 1024 * 1024];
__device__ uint16_t g_kv[(size_t)8  * 1024 * 1024];   // cross-attn K|V packed
__device__ uint16_t g_f [(size_t)16 * 1024 * 1024];
__device__ uint16_t g_w [(size_t)16 * 1024 * 1024];

// g_w layout (units of 1M = E*E halves):
// 0:Wq_s 1:Wk_s 2:Wv_s 3:proj_s 4:Wq_c 5:Wk_c 6:Wv_c 7:proj_c 8..11:w1 12..15:w2
constexpr size_t WU = (size_t)1024 * 1024;

// -------------------------- asm helpers ------------------------------------
__device__ __forceinline__ uint32_t smem_u32(const void* p) {
    uint32_t a;
    asm("{ .reg .u64 t; cvta.to.shared.u64 t, %1; cvt.u32.u64 %0, t; }" : "=r"(a) : "l"(p));
    return a;
}
#define CP16(s, g) \
    asm volatile("cp.async.cg.shared.global [%0], [%1], 16;" :: "r"(s), "l"(g))
#define CP_COMMIT()  asm volatile("cp.async.commit_group;" ::: "memory")
#define CP_WAIT0()   asm volatile("cp.async.wait_group 0;" ::: "memory")
#define CP_WAIT1()   asm volatile("cp.async.wait_group 1;" ::: "memory")

#define LDSM4(r, addr)                                                        \
    asm volatile("ldmatrix.sync.aligned.m8n8.x4.shared.b16 {%0,%1,%2,%3}, [%4];" \
        : "=r"((r)[0]), "=r"((r)[1]), "=r"((r)[2]), "=r"((r)[3]) : "r"(addr))
#define LDSM4T(r, addr)                                                       \
    asm volatile("ldmatrix.sync.aligned.m8n8.x4.trans.shared.b16 {%0,%1,%2,%3}, [%4];" \
        : "=r"((r)[0]), "=r"((r)[1]), "=r"((r)[2]), "=r"((r)[3]) : "r"(addr))

#define MMAH(d, a, b0, b1)                                                    \
    asm("mma.sync.aligned.m16n8k16.row.col.f32.f16.f16.f32 "                  \
        "{%0,%1,%2,%3},{%4,%5,%6,%7},{%8,%9},{%0,%1,%2,%3};"                  \
        : "+f"((d)[0]), "+f"((d)[1]), "+f"((d)[2]), "+f"((d)[3])              \
        : "r"((a)[0]), "r"((a)[1]), "r"((a)[2]), "r"((a)[3]), "r"(b0), "r"(b1))

__device__ __forceinline__ uint32_t packh2(float lo, float hi) {
    __half2 h = __floats2half2_rn(lo, hi);
    return *reinterpret_cast<uint32_t*>(&h);
}
__device__ __forceinline__ unsigned short h16(float x) {
    __half h = __float2half_rn(x);
    return *reinterpret_cast<unsigned short*>(&h);
}
__device__ __forceinline__ float gelu_f(float x) {
    return 0.5f * x * (1.0f + erff(x * 0.7071067811865475f));
}

// ---------------------------------------------------------------------------
// fp16 HMMA GEMM (R9 config): C[M,N] = epi(A[M,K] * B[N,K]^T)
// 128x128 tile, 64x32 warp tiles (2x4), K chunks of 64, 3-stage cp.async
// ring, one syncthreads per chunk, 2 CTAs/SM.
// ---------------------------------------------------------------------------
constexpr int H_OFF_B = 16384;
constexpr int H_STAGE = 32768;
constexpr int GEMM_SMEM = 3 * H_STAGE + 1024;

__global__ void __launch_bounds__(256, 2)
hgemm(const uint16_t* __restrict__ A, const uint16_t* __restrict__ Bm,
      const float* __restrict__ bias, const float* __restrict__ res,
      float* __restrict__ C, uint16_t* __restrict__ Ch,
      int N, int K, int do_gelu) {
    extern __shared__ uint8_t dsm[];
    uint8_t* tiles = (uint8_t*)(((uintptr_t)dsm + 1023) & ~(uintptr_t)1023);
    const uint32_t tb = smem_u32(tiles);

    const int tid  = threadIdx.x;
    const int lane = tid & 31;
    const int wid  = tid >> 5;
    const int wr   = wid >> 2;
    const int wc   = wid & 3;
    const int row0 = blockIdx.y * 128;
    const int col0 = blockIdx.x * 128;

    const int lrow = tid >> 1, lhalf = tid & 1;
    uint32_t so[4];
#pragma unroll
    for (int i = 0; i < 4; i++) {
        uint32_t o = (uint32_t)lrow * 128 + (uint32_t)lhalf * 64 + i * 16;
        so[i] = o ^ ((o >> 3) & 0x70);
    }
    const size_t a_base = (size_t)(row0 + lrow) * K + lhalf * 32;
    const size_t b_base = (size_t)(col0 + lrow) * K + lhalf * 32;

    const int ka = (lane >> 4) * 16;
    const int kb = ((lane >> 3) & 1) * 16;
    uint32_t aoff[4], xA[4];
#pragma unroll
    for (int mt = 0; mt < 4; mt++) {
        int r = wr * 64 + mt * 16 + (lane & 15);
        aoff[mt] = (uint32_t)r * 128;
        xA[mt] = (uint32_t)(r & 7) * 16;
    }
    uint32_t boff[2], xB[2];
#pragma unroll
    for (int p = 0; p < 2; p++) {
        int r = wc * 32 + p * 16 + ((lane >> 4) & 1) * 8 + (lane & 7);
        boff[p] = (uint32_t)r * 128;
        xB[p] = (uint32_t)(r & 7) * 16;
    }

    float acc[4][4][4];
#pragma unroll
    for (int mt = 0; mt < 4; mt++)
#pragma unroll
        for (int nt = 0; nt < 4; nt++)
#pragma unroll
            for (int e = 0; e < 4; e++) acc[mt][nt][e] = 0.0f;

    const int NC = K >> 6;
#pragma unroll
    for (int pc = 0; pc < 2; pc++) {
        if (pc < NC) {
            const uint32_t st = tb + pc * H_STAGE;
            const int kc = pc << 6;
#pragma unroll
            for (int i = 0; i < 4; i++) {
                CP16(st + so[i],           A  + a_base + kc + i * 8);
                CP16(st + H_OFF_B + so[i], Bm + b_base + kc + i * 8);
            }
            CP_COMMIT();
        }
    }

    int stage = 0;
    for (int c = 0; c < NC; c++) {
        if (c + 1 < NC) CP_WAIT1(); else CP_WAIT0();
        __syncthreads();   // chunk c ready; stage (c+2)%3 free

        if (c + 2 < NC) {
            int pst = stage + 2; if (pst >= 3) pst -= 3;
            const uint32_t st = tb + pst * H_STAGE;
            const int kc = (c + 2) << 6;
#pragma unroll
            for (int i = 0; i < 4; i++) {
                CP16(st + so[i],           A  + a_base + kc + i * 8);
                CP16(st + H_OFF_B + so[i], Bm + b_base + kc + i * 8);
            }
            CP_COMMIT();
        }

        const uint32_t sb = tb + stage * H_STAGE;
#pragma unroll
        for (int ks = 0; ks < 4; ks++) {
            uint32_t ah[4][4], bh[2][4];
            const uint32_t cba = (uint32_t)(ks * 32 + ka);
#pragma unroll
            for (int mt = 0; mt < 4; mt++)
                LDSM4(ah[mt], sb + aoff[mt] + (cba ^ xA[mt]));
            const uint32_t cbb = (uint32_t)(ks * 32 + kb);
#pragma unroll
            for (int p = 0; p < 2; p++)
                LDSM4(bh[p], sb + H_OFF_B + boff[p] + (cbb ^ xB[p]));
#pragma unroll
            for (int mt = 0; mt < 4; mt++)
#pragma unroll
                for (int nt = 0; nt < 4; nt++) {
                    const int p = nt >> 1, q = (nt & 1) * 2;
                    MMAH(acc[mt][nt], ah[mt], bh[p][q], bh[p][q + 1]);
                }
        }
        if (++stage == 3) stage = 0;
    }

    const int mrow = lane >> 2;
    const int ncol = (lane & 3) * 2;
#pragma unroll
    for (int mt = 0; mt < 4; mt++) {
#pragma unroll
        for (int half = 0; half < 2; half++) {
            const int r = row0 + wr * 64 + mt * 16 + mrow + half * 8;
#pragma unroll
            for (int nt = 0; nt < 4; nt++) {
                float v0 = acc[mt][nt][half * 2 + 0];
                float v1 = acc[mt][nt][half * 2 + 1];
                const int cc = col0 + wc * 32 + nt * 8 + ncol;
                if (bias) { v0 += bias[cc]; v1 += bias[cc + 1]; }
                if (do_gelu) { v0 = gelu_f(v0); v1 = gelu_f(v1); }
                if (res) {
                    v0 += res[(size_t)r * N + cc];
                    v1 += res[(size_t)r * N + cc + 1];
                }
                if (C) *(float2*)(C + (size_t)r * N + cc) = make_float2(v0, v1);
                if (Ch) *(uint32_t*)(Ch + (size_t)r * N + cc) = packh2(v0, v1);
            }
        }
    }
}

// ---------------------------------------------------------------------------
// Fused flash attention, fp16, 3-stage KV ring (R9, validated).
// ---------------------------------------------------------------------------
constexpr int F_KV0 = 16384;
constexpr int F_V   = 16384;
constexpr int F_STG = 32768;
constexpr int FLASH_SMEM = 16384 + 3 * F_STG + 1024;

__global__ void __launch_bounds__(256, 1)
flash_h(const uint16_t* __restrict__ Q, const uint16_t* __restrict__ Kp,
        const uint16_t* __restrict__ Vp, uint16_t* __restrict__ Oh,
        int Tq, int Tk, int strQ, int strKV, int causal) {
    extern __shared__ uint8_t dsm[];
    uint8_t* basep = (uint8_t*)(((uintptr_t)dsm + 1023) & ~(uintptr_t)1023);
    const uint32_t tb = smem_u32(basep);

    const int bh = blockIdx.y;
    const int b = bh >> 4, h = bh & 15;
    int it = blockIdx.x;
    if (causal) it = (int)gridDim.x - 1 - it;
    const int i0 = it * 128;
    const int NJ = causal ? (it + 1) : (Tk >> 7);

    const int tid = threadIdx.x;
    const int lane = tid & 31;
    const int wid = tid >> 5;

    const int lrow = tid >> 1, lhalf = tid & 1;
    uint32_t so[4];
#pragma unroll
    for (int i = 0; i < 4; i++) {
        uint32_t o = (uint32_t)lrow * 128 + (uint32_t)lhalf * 64 + i * 16;
        so[i] = o ^ ((o >> 3) & 0x70);
    }
    const size_t qg = (size_t)(b * Tq + i0 + lrow) * strQ + h * cfg::HD + lhalf * 32;
    const size_t kg = (size_t)(b * Tk + lrow) * strKV + h * cfg::HD + lhalf * 32;

#pragma unroll
    for (int i = 0; i < 4; i++) CP16(tb + so[i], Q + qg + i * 8);
    {
        const uint32_t st = tb + F_KV0;
#pragma unroll
        for (int i = 0; i < 4; i++) {
            CP16(st + so[i],       Kp + kg + i * 8);
            CP16(st + F_V + so[i], Vp + kg + i * 8);
        }
        CP_COMMIT();
    }
    if (1 < NJ) {
        const uint32_t st = tb + F_KV0 + F_STG;
        const size_t kg1 = kg + (size_t)128 * strKV;
#pragma unroll
        for (int i = 0; i < 4; i++) {
            CP16(st + so[i],       Kp + kg1 + i * 8);
            CP16(st + F_V + so[i], Vp + kg1 + i * 8);
        }
        CP_COMMIT();
    }

    const int arow = wid * 16 + (lane & 15);
    const uint32_t aoff = (uint32_t)arow * 128;
    const uint32_t axr  = (uint32_t)(arow & 7) * 16;
    const int ka = (lane >> 4) * 16;
    const int nrow_b = ((lane >> 4) & 1) * 8 + (lane & 7);
    const int kb = ((lane >> 3) & 1) * 16;
    const int vm = lane >> 3;
    const int vrow_b = (vm & 1) * 8 + (lane & 7);
    const int vcol_b = (vm >> 1) * 16;

    uint32_t qf[4][4];
    float accO[8][4];
#pragma unroll
    for (int nt = 0; nt < 8; nt++)
#pragma unroll
        for (int e = 0; e < 4; e++) accO[nt][e] = 0.0f;
    float m2[2] = {-3.0e38f, -3.0e38f};
    float lsum[2] = {0.0f, 0.0f};

    const int mrow = lane >> 2;
    const int cb = (lane & 3) * 2;
    const int irow0 = i0 + wid * 16 + mrow;
    const int irow1 = irow0 + 8;

    int stage = 0;
    for (int jt = 0; jt < NJ; jt++) {
        if (jt + 1 < NJ) CP_WAIT1(); else CP_WAIT0();
        __syncthreads();

        if (jt + 2 < NJ) {
            int pst = stage + 2; if (pst >= 3) pst -= 3;
            const uint32_t st = tb + F_KV0 + pst * F_STG;
            const size_t kgj = kg + (size_t)(jt + 2) * 128 * strKV;
#pragma unroll
            for (int i = 0; i < 4; i++) {
                CP16(st + so[i],       Kp + kgj + i * 8);
                CP16(st + F_V + so[i], Vp + kgj + i * 8);
            }
            CP_COMMIT();
        }

        if (jt == 0) {
#pragma unroll
            for (int ks = 0; ks < 4; ks++)
                LDSM4(qf[ks], tb + aoff + (((uint32_t)(ks * 32 + ka)) ^ axr));
        }
        const uint32_t sb = tb + F_KV0 + stage * F_STG;

        float accS[16][4];
#pragma unroll
        for (int nt = 0; nt < 16; nt++)
#pragma unroll
            for (int e = 0; e < 4; e++) accS[nt][e] = 0.0f;

#pragma unroll
        for (int ks = 0; ks < 4; ks++) {
            const uint32_t cbb = (uint32_t)(ks * 32 + kb);
#pragma unroll
            for (int ntp = 0; ntp < 8; ntp++) {
                const int r = ntp * 16 + nrow_b;
                uint32_t bf4[4];
                LDSM4(bf4, sb + (uint32_t)r * 128 + (cbb ^ ((uint32_t)(r & 7) * 16)));
                MMAH(accS[2 * ntp],     qf[ks], bf4[0], bf4[1]);
                MMAH(accS[2 * ntp + 1], qf[ks], bf4[2], bf4[3]);
            }
        }

        const int j0 = jt * 128;
        const bool maskTile = causal && (jt == NJ - 1);
#pragma unroll
        for (int nt = 0; nt < 16; nt++)
#pragma unroll
            for (int e = 0; e < 4; e++) accS[nt][e] *= cfg::SC2;
        if (maskTile) {
#pragma unroll
            for (int nt = 0; nt < 16; nt++) {
                const int jc = j0 + nt * 8 + cb;
                if (jc     > irow0) accS[nt][0] = -3.0e38f;
                if (jc + 1 > irow0) accS[nt][1] = -3.0e38f;
                if (jc     > irow1) accS[nt][2] = -3.0e38f;
                if (jc + 1 > irow1) accS[nt][3] = -3.0e38f;
            }
        }

        float mx0 = -3.0e38f, mx1 = -3.0e38f;
#pragma unroll
        for (int nt = 0; nt < 16; nt++) {
            mx0 = fmaxf(mx0, fmaxf(accS[nt][0], accS[nt][1]));
            mx1 = fmaxf(mx1, fmaxf(accS[nt][2], accS[nt][3]));
        }
        mx0 = fmaxf(mx0, __shfl_xor_sync(0xffffffffu, mx0, 1));
        mx0 = fmaxf(mx0, __shfl_xor_sync(0xffffffffu, mx0, 2));
        mx1 = fmaxf(mx1, __shfl_xor_sync(0xffffffffu, mx1, 1));
        mx1 = fmaxf(mx1, __shfl_xor_sync(0xffffffffu, mx1, 2));
        const float mn0 = fmaxf(m2[0], mx0);
        const float mn1 = fmaxf(m2[1], mx1);
        const float al0 = exp2f(m2[0] - mn0);
        const float al1 = exp2f(m2[1] - mn1);
        m2[0] = mn0; m2[1] = mn1;

        float s0 = 0.0f, s1 = 0.0f;
#pragma unroll
        for (int nt = 0; nt < 16; nt++) {
            float p0 = exp2f(accS[nt][0] - mn0);
            float p1 = exp2f(accS[nt][1] - mn0);
            float p2 = exp2f(accS[nt][2] - mn1);
            float p3 = exp2f(accS[nt][3] - mn1);
            accS[nt][0] = p0; accS[nt][1] = p1;
            accS[nt][2] = p2; accS[nt][3] = p3;
            s0 += p0 + p1;
            s1 += p2 + p3;
        }
        s0 += __shfl_xor_sync(0xffffffffu, s0, 1);
        s0 += __shfl_xor_sync(0xffffffffu, s0, 2);
        s1 += __shfl_xor_sync(0xffffffffu, s1, 1);
        s1 += __shfl_xor_sync(0xffffffffu, s1, 2);
        lsum[0] = lsum[0] * al0 + s0;
        lsum[1] = lsum[1] * al1 + s1;

#pragma unroll
        for (int nt = 0; nt < 8; nt++) {
            accO[nt][0] *= al0; accO[nt][1] *= al0;
            accO[nt][2] *= al1; accO[nt][3] *= al1;
        }

#pragma unroll
        for (int ks = 0; ks < 8; ks++) {
            uint32_t ph[4];
#pragma unroll
            for (int q = 0; q < 2; q++) {
                ph[2 * q]     = packh2(accS[2 * ks + q][0], accS[2 * ks + q][1]);
                ph[2 * q + 1] = packh2(accS[2 * ks + q][2], accS[2 * ks + q][3]);
            }
            const int jr = ks * 16 + vrow_b;
            const uint32_t roff = (uint32_t)jr * 128;
            const uint32_t xr = (uint32_t)(jr & 7) * 16;
#pragma unroll
            for (int ntp = 0; ntp < 4; ntp++) {
                uint32_t vf4[4];
                LDSM4T(vf4, sb + F_V + roff + (((uint32_t)(ntp * 32 + vcol_b)) ^ xr));
                MMAH(accO[2 * ntp],     ph, vf4[0], vf4[1]);
                MMAH(accO[2 * ntp + 1], ph, vf4[2], vf4[3]);
            }
        }
        if (++stage == 3) stage = 0;
    }

    const float li0 = 1.0f / lsum[0];
    const float li1 = 1.0f / lsum[1];
#pragma unroll
    for (int nt = 0; nt < 8; nt++) {
        const int d = h * cfg::HD + nt * 8 + cb;
        const size_t o0 = (size_t)(b * Tq + irow0) * cfg::E + d;
        const size_t o1 = (size_t)(b * Tq + irow1) * cfg::E + d;
        *(uint32_t*)(Oh + o0) = packh2(accO[nt][0] * li0, accO[nt][1] * li0);
        *(uint32_t*)(Oh + o1) = packh2(accO[nt][2] * li1, accO[nt][3] * li1);
    }
}

// ---------------------------------------------------------------------------
// Weight prep + context convert, ONE launch.
// ids [0,8192): eight ExE weights; [8192,12288): w1; [12288,16384): w2;
// ids [16384,17408): context fp32 -> fp16 elementwise (1024 float4 each).
// ---------------------------------------------------------------------------
__global__ void prep_weights(
    const float* __restrict__ Wq_s, const float* __restrict__ Wk_s,
    const float* __restrict__ Wv_s, const float* __restrict__ proj_s,
    const float* __restrict__ Wq_c, const float* __restrict__ Wk_c,
    const float* __restrict__ Wv_c, const float* __restrict__ proj_c,
    const float* __restrict__ w1,   const float* __restrict__ w2,
    const float* __restrict__ ctx,  uint16_t* __restrict__ Ch,
    uint16_t* __restrict__ Wdst) {
    const int id = blockIdx.x;
    const int tx = threadIdx.x, ty = threadIdx.y;

    if (id >= 16384) {
        const int t = id - 16384;
        const int lin = ty * 32 + tx;                 // 0..255
        const size_t base4 = (size_t)t * 1024 + lin;  // float4 index
        const float4* src = (const float4*)ctx;
        ushort4* dst = (ushort4*)Ch;
#pragma unroll
        for (int i = 0; i < 4; i++) {
            const float4 v = src[base4 + i * 256];
            ushort4 o;
            o.x = h16(v.x); o.y = h16(v.y); o.z = h16(v.z); o.w = h16(v.w);
            dst[base4 + i * 256] = o;
        }
        return;
    }

    __shared__ float tile[32][33];
    const float* W;
    uint16_t* H;
    int n0, k0, Kd, Nd;
    if (id < 8192) {
        const int w = id >> 10, t = id & 1023;
        const float* srcs[8] = {Wq_s, Wk_s, Wv_s, proj_s, Wq_c, Wk_c, Wv_c, proj_c};
        W = srcs[w];
        H = Wdst + (size_t)w * WU;
        n0 = (t & 31) * 32; k0 = (t >> 5) * 32;
        Kd = cfg::E; Nd = cfg::E;
    } else if (id < 12288) {
        const int t = id - 8192;                 // w1: [E,4E] -> [4E,E]
        W = w1; H = Wdst + 8 * WU;
        n0 = (t & 127) * 32; k0 = (t >> 7) * 32;
        Kd = cfg::E; Nd = 4 * cfg::E;
    } else {
        const int t = id - 12288;                // w2: [4E,E] -> [E,4E]
        W = w2; H = Wdst + 12 * WU;
        n0 = (t & 31) * 32; k0 = (t >> 5) * 32;
        Kd = 4 * cfg::E; Nd = cfg::E;
    }
    for (int r = ty; r < 32; r += 8)
        tile[r][tx] = W[(size_t)(k0 + r) * Nd + n0 + tx];
    __syncthreads();
    for (int r = ty; r < 32; r += 8)
        H[(size_t)(n0 + r) * Kd + k0 + tx] = h16(tile[tx][r]);
}

// ---------------------------------------------------------------------------
// LayerNorm -> fp16
// ---------------------------------------------------------------------------
__global__ void ln_h(const float* __restrict__ X, const float* __restrict__ gam,
                     const float* __restrict__ bet, uint16_t* __restrict__ H) {
    __shared__ float red[256];
    const int row = blockIdx.x;
    const int tid = threadIdx.x;
    const float4 v = ((const float4*)(X + (size_t)row * cfg::E))[tid];

    float s = v.x + v.y + v.z + v.w;
    red[tid] = s; __syncthreads();
    for (int off = 128; off; off >>= 1) {
        if (tid < off) red[tid] += red[tid + off];
        __syncthreads();
    }
    const float mu = red[0] * (1.0f / cfg::E);
    __syncthreads();

    const float dx = v.x - mu, dy = v.y - mu, dz = v.z - mu, dw = v.w - mu;
    red[tid] = dx*dx + dy*dy + dz*dz + dw*dw; __syncthreads();
    for (int off = 128; off; off >>= 1) {
        if (tid < off) red[tid] += red[tid + off];
        __syncthreads();
    }
    const float var = red[0] * (1.0f / cfg::E);
    const float r = rsqrtf(var + 1e-5f);

    const float4 g4 = ((const float4*)gam)[tid];
    const float4 b4 = ((const float4*)bet)[tid];
    ushort4 o;
    o.x = h16(dx * r * g4.x + b4.x);
    o.y = h16(dy * r * g4.y + b4.y);
    o.z = h16(dz * r * g4.z + b4.z);
    o.w = h16(dw * r * g4.w + b4.w);
    ((ushort4*)(H + (size_t)row * cfg::E))[tid] = o;
}

// ---------------------------------------------------------------------------
// Launch sequence
// ---------------------------------------------------------------------------
extern "C" void kernel_launch(void* const* d_in, const int* in_sizes, int n_in,
                              void* d_out, int out_size) {
    using namespace cfg;
    const float* x        = (const float*)d_in[0];
    const float* context  = (const float*)d_in[1];
    const float* ln1_g    = (const float*)d_in[2];
    const float* ln1_b    = (const float*)d_in[3];
    const float* ln2_g    = (const float*)d_in[4];
    const float* ln2_b    = (const float*)d_in[5];
    const float* ln3_g    = (const float*)d_in[6];
    const float* ln3_b    = (const float*)d_in[7];
    const float* Wq_s     = (const float*)d_in[8];
    const float* Wk_s     = (const float*)d_in[9];
    const float* Wv_s     = (const float*)d_in[10];
    const float* proj_s_w = (const float*)d_in[11];
    const float* proj_s_b = (const float*)d_in[12];
    const float* Wq_c     = (const float*)d_in[13];
    const float* Wk_c     = (const float*)d_in[14];
    const float* Wv_c     = (const float*)d_in[15];
    const float* proj_c_w = (const float*)d_in[16];
    const float* proj_c_b = (const float*)d_in[17];
    const float* w1       = (const float*)d_in[18];
    const float* b1       = (const float*)d_in[19];
    const float* w2       = (const float*)d_in[20];
    const float* b2       = (const float*)d_in[21];
    float* out = (float*)d_out;

    float *px1, *px2;
    uint16_t *ah, *ch, *qh, *kvh, *fh, *wh;
    cudaGetSymbolAddress((void**)&px1, g_x1);
    cudaGetSymbolAddress((void**)&px2, g_x2);
    cudaGetSymbolAddress((void**)&ah,  g_a);
    cudaGetSymbolAddress((void**)&ch,  g_c);
    cudaGetSymbolAddress((void**)&qh,  g_q);
    cudaGetSymbolAddress((void**)&kvh, g_kv);
    cudaGetSymbolAddress((void**)&fh,  g_f);
    cudaGetSymbolAddress((void**)&wh,  g_w);

    cudaFuncSetAttribute(hgemm,   cudaFuncAttributeMaxDynamicSharedMemorySize, GEMM_SMEM);
    cudaFuncSetAttribute(flash_h, cudaFuncAttributeMaxDynamicSharedMemorySize, FLASH_SMEM);

    const int M = B * T;
    const dim3 gE   (E / 128,     M / 128);
    const dim3 gQKV (3 * E / 128, M / 128);
    const dim3 gKV  (2 * E / 128, M / 128);
    const dim3 g4E  (4 * E / 128, M / 128);
    const dim3 gfl  (T / 128, BH);
    const dim3 tbt(32, 8);

    // ---- one-shot prep: all weights + context fp16 ----
    prep_weights<<<17408, tbt>>>(Wq_s, Wk_s, Wv_s, proj_s_w,
                                 Wq_c, Wk_c, Wv_c, proj_c_w, w1, w2,
                                 context, ch, wh);

    // ---- cross-attn KV GEMM early, into DEDICATED buffer (R14 bug fix) ----
    hgemm<<<gKV, 256, GEMM_SMEM>>>(ch, wh + 5 * WU, nullptr, nullptr,
                                   nullptr, kvh, 2 * E, E, 0);

    // ---- self attention (causal): merged QKV (units 0,1,2) ----
    ln_h<<<M, 256>>>(x, ln1_g, ln1_b, ah);
    hgemm<<<gQKV, 256, GEMM_SMEM>>>(ah, wh, nullptr, nullptr,
                                    nullptr, fh, 3 * E, E, 0);
    flash_h<<<gfl, 256, FLASH_SMEM>>>(fh, fh + E, fh + 2 * E, qh, T, S, 3 * E, 3 * E, 1);
    hgemm<<<gE, 256, GEMM_SMEM>>>(qh, wh + 3 * WU, proj_s_b, x, px1, nullptr, E, E, 0);

    // ---- cross attention (context NOT normalized) ----
    ln_h<<<M, 256>>>(px1, ln2_g, ln2_b, ah);
    hgemm<<<gE, 256, GEMM_SMEM>>>(ah, wh + 4 * WU, nullptr, nullptr, nullptr, qh, E, E, 0);
    flash_h<<<gfl, 256, FLASH_SMEM>>>(qh, kvh, kvh + E, ah, T, S, E, 2 * E, 0);
    hgemm<<<gE, 256, GEMM_SMEM>>>(ah, wh + 7 * WU, proj_c_b, px1, px2, nullptr, E, E, 0);

    // ---- FFN ----
    ln_h<<<M, 256>>>(px2, ln3_g, ln3_b, qh);
    hgemm<<<g4E, 256, GEMM_SMEM>>>(qh, wh + 8 * WU, b1, nullptr, nullptr, fh, 4 * E, E, 1);
    hgemm<<<gE, 256, GEMM_SMEM>>>(fh, wh + 12 * WU, b2, px2, out, nullptr, E, 4 * E, 0);
}